// round 12
// baseline (speedup 1.0000x reference)
#include <cuda_runtime.h>
#include <cuda_bf16.h>
#include <cstdint>
#include <cstddef>

// Fixed shapes per reference: B=16, N=8192, C=256, M=2048
#define NB    16
#define NP    8192
#define NC    256
#define MS    2048
#define TPB   256
#define PPT   (NP / TPB)       // 32 points per thread
#define NPAIR (PPT / 2)        // 16 packed pairs per thread
#define NW    (TPB / 32)       // 8 warps
#define NCHUNK 4               // 4 chunks of 8 points for the argmax scan

// Scratch for selected indices (device global: no allocation allowed)
__device__ int g_idx[NB * MS];

// ---- packed f32x2 helpers (bit-exact per lane vs scalar) ------------------
__device__ __forceinline__ unsigned long long pk2(float lo, float hi) {
    unsigned long long r;
    asm("mov.b64 %0, {%1, %2};" : "=l"(r) : "f"(lo), "f"(hi));
    return r;
}
__device__ __forceinline__ void up2(unsigned long long v, float& lo, float& hi) {
    asm("mov.b64 {%0, %1}, %2;" : "=f"(lo), "=f"(hi) : "l"(v));
}
__device__ __forceinline__ unsigned long long add2(unsigned long long a,
                                                   unsigned long long b) {
    unsigned long long r;
    asm("add.rn.f32x2 %0, %1, %2;" : "=l"(r) : "l"(a), "l"(b));
    return r;
}
__device__ __forceinline__ unsigned long long mul2(unsigned long long a,
                                                   unsigned long long b) {
    unsigned long long r;
    asm("mul.rn.f32x2 %0, %1, %2;" : "=l"(r) : "l"(a), "l"(b));
    return r;
}
__device__ __forceinline__ unsigned long long fma2(unsigned long long a,
                                                   unsigned long long b,
                                                   unsigned long long c) {
    unsigned long long r;
    asm("fma.rn.f32x2 %0, %1, %2, %3;" : "=l"(r) : "l"(a), "l"(b), "l"(c));
    return r;
}

// 64-bit argmax key: dist >= 0 so float bits order == value order.
// key = (bits << 13) | (8191 - idx): max key => max value, min index on ties.
__device__ __forceinline__ unsigned long long make_key(unsigned int vbits, int idx) {
    return ((unsigned long long)vbits << 13)
         | (unsigned long long)(8191 - idx);
}
__device__ __forceinline__ unsigned long long umax64(unsigned long long a,
                                                     unsigned long long b) {
    return a > b ? a : b;
}

// ---------------------------------------------------------------------------
// FPS: one CTA per batch, 8 warps. Points + min-dist register-resident.
// Per iter: chunked (4x8) argmax-index recovery (short dependency chains),
// 2x REDUX (warp), STS key[warp], ONE barrier, redundant 8-way key max.
// ---------------------------------------------------------------------------
__global__ __launch_bounds__(TPB, 1)
void fps_kernel(const float* __restrict__ pts)
{
    extern __shared__ float sm[];           // sx[NP], sy[NP], sz[NP] = 96 KB
    float* sx = sm;
    float* sy = sm + NP;
    float* sz = sm + 2 * NP;

    __shared__ unsigned long long s_key[2][NW];   // double-buffered by parity
    __shared__ double s_ax[NW], s_ay[NW], s_az[NW];

    const int t    = threadIdx.x;
    const int b    = blockIdx.x;
    const int lane = t & 31;
    const int warp = t >> 5;

    const float* base = pts + (size_t)b * 3 * NP;

    // Stage points into shared memory (coalesced; input layout [3, N])
    for (int i = t; i < NP; i += TPB) {
        sx[i] = base[i];
        sy[i] = base[NP + i];
        sz[i] = base[2 * NP + i];
    }
    __syncthreads();

    // Register-resident packed copy: pair (2j,2j+1) -> indices t+2j*TPB, t+(2j+1)*TPB
    unsigned long long x2[NPAIR], y2[NPAIR], z2[NPAIR];
    float dist[PPT];
#pragma unroll
    for (int j = 0; j < NPAIR; j++) {
        int i0 = t + (2 * j) * TPB;
        int i1 = i0 + TPB;
        x2[j] = pk2(sx[i0], sx[i1]);
        y2[j] = pk2(sy[i0], sy[i1]);
        z2[j] = pk2(sz[i0], sz[i1]);
        dist[2 * j]     = 1e10f;
        dist[2 * j + 1] = 1e10f;
    }

    // ---- Centroid (double accumulation; runs once) -------------------------
    double ax = 0.0, ay = 0.0, az = 0.0;
#pragma unroll
    for (int j = 0; j < NPAIR; j++) {
        float a0, a1;
        up2(x2[j], a0, a1); ax += (double)a0 + (double)a1;
        up2(y2[j], a0, a1); ay += (double)a0 + (double)a1;
        up2(z2[j], a0, a1); az += (double)a0 + (double)a1;
    }
#pragma unroll
    for (int o = 16; o > 0; o >>= 1) {
        ax += __shfl_down_sync(0xffffffffu, ax, o);
        ay += __shfl_down_sync(0xffffffffu, ay, o);
        az += __shfl_down_sync(0xffffffffu, az, o);
    }
    if (lane == 0) { s_ax[warp] = ax; s_ay[warp] = ay; s_az[warp] = az; }
    __syncthreads();
    if (warp == 0) {
        ax = (lane < NW) ? s_ax[lane] : 0.0;
        ay = (lane < NW) ? s_ay[lane] : 0.0;
        az = (lane < NW) ? s_az[lane] : 0.0;
#pragma unroll
        for (int o = 4; o > 0; o >>= 1) {
            ax += __shfl_down_sync(0xffffffffu, ax, o);
            ay += __shfl_down_sync(0xffffffffu, ay, o);
            az += __shfl_down_sync(0xffffffffu, az, o);
        }
        if (lane == 0) { s_ax[0] = ax; s_ay[0] = ay; s_az[0] = az; }
    }
    __syncthreads();
    const float cx0 = (float)(s_ax[0] / (double)NP);
    const float cy0 = (float)(s_ay[0] / (double)NP);
    const float cz0 = (float)(s_az[0] / (double)NP);

    // ---- Initial farthest = argmax dist-to-centroid (first-index ties) -----
    unsigned long long keyreg;
    {
        const unsigned long long ncx = pk2(-cx0, -cx0);
        const unsigned long long ncy = pk2(-cy0, -cy0);
        const unsigned long long ncz = pk2(-cz0, -cz0);
        float bv = -1e30f;
        int   bi = 0;
#pragma unroll
        for (int j = 0; j < NPAIR; j++) {
            unsigned long long dx = add2(x2[j], ncx);
            unsigned long long dy = add2(y2[j], ncy);
            unsigned long long dz = add2(z2[j], ncz);
            unsigned long long d  = mul2(dx, dx);
            d = fma2(dy, dy, d);
            d = fma2(dz, dz, d);
            float d0, d1;
            up2(d, d0, d1);
            int i0 = t + (2 * j) * TPB;
            if (d0 > bv) { bv = d0; bi = i0; }        // ascending idx => strict >
            if (d1 > bv) { bv = d1; bi = i0 + TPB; }
        }
        unsigned int vb = __float_as_uint(fmaxf(bv, 0.0f));   // safety clamp (once)
        unsigned int wv = __reduce_max_sync(0xffffffffu, vb);
        int cand = (vb == wv) ? bi : 0x7fffffff;
        int mi = __reduce_min_sync(0xffffffffu, cand);
        if (lane == 0) s_key[1][warp] = make_key(wv, mi);
        __syncthreads();
        const unsigned long long* k = s_key[1];
        unsigned long long m0 = umax64(k[0], k[1]);
        unsigned long long m1 = umax64(k[2], k[3]);
        unsigned long long m2 = umax64(k[4], k[5]);
        unsigned long long m3 = umax64(k[6], k[7]);
        keyreg = umax64(umax64(m0, m1), umax64(m2, m3));
    }

    // ---- Main sequential loop: ONE barrier, no atomics ---------------------
    for (int m = 0; m < MS; m++) {
        const int par = m & 1;
        const int far = 8191 - (int)(keyreg & 8191ULL);
        if (t == 0) g_idx[b * MS + m] = far;

        const float cx = sx[far];   // broadcast LDS
        const float cy = sy[far];
        const float cz = sz[far];
        const unsigned long long ncx = pk2(-cx, -cx);
        const unsigned long long ncy = pk2(-cy, -cy);
        const unsigned long long ncz = pk2(-cz, -cz);

        // Chunked processing: 4 chunks x 4 pairs (8 points). Each chunk gets
        // its own max tree + short index scan => 4 independent short chains
        // instead of one 32-long serial SEL chain.
        float cv[NCHUNK];
        int   ck[NCHUNK];                 // winning k within chunk (0..7)
#pragma unroll
        for (int c = 0; c < NCHUNK; c++) {
            float n[8];
#pragma unroll
            for (int q = 0; q < 4; q++) {
                const int j = c * 4 + q;
                unsigned long long dx = add2(x2[j], ncx);   // x + (-c) == x - c exactly
                unsigned long long dy = add2(y2[j], ncy);
                unsigned long long dz = add2(z2[j], ncz);
                unsigned long long d  = mul2(dx, dx);
                d = fma2(dy, dy, d);
                d = fma2(dz, dz, d);
                float d0, d1;
                up2(d, d0, d1);
                float n0 = fminf(dist[2 * j],     d0);
                float n1 = fminf(dist[2 * j + 1], d1);
                dist[2 * j]     = n0;
                dist[2 * j + 1] = n1;
                n[2 * q]     = n0;
                n[2 * q + 1] = n1;
            }
            // chunk max: balanced tree (depth 3)
            float m01 = fmaxf(n[0], n[1]);
            float m23 = fmaxf(n[2], n[3]);
            float m45 = fmaxf(n[4], n[5]);
            float m67 = fmaxf(n[6], n[7]);
            float mA  = fmaxf(m01, m23);
            float mB  = fmaxf(m45, m67);
            float v   = fmaxf(mA, mB);
            cv[c] = v;
            // within-chunk min-k scan (descending => smallest matching k wins;
            // FMNMX preserves bit patterns exactly, so == is reliable)
            int kk = 0;
#pragma unroll
            for (int q = 7; q >= 0; q--)
                if (n[q] == v) kk = q;
            ck[c] = kk;
        }

        // Combine chunks in ascending order with strict > (earliest chunk
        // wins ties => smallest k => smallest index).
        float bv  = cv[0];
        int   bk  = ck[0];                // global k in 0..31
#pragma unroll
        for (int c = 1; c < NCHUNK; c++) {
            bool take = cv[c] > bv;
            bv = take ? cv[c] : bv;
            bk = take ? (c * 8 + ck[c]) : bk;
        }
        const int bi = t + bk * TPB;

        // Warp: single-instruction max on bits (dists >= 0), then min index.
        unsigned int vb = __float_as_uint(bv);
        unsigned int wv = __reduce_max_sync(0xffffffffu, vb);
        int cand = (vb == wv) ? bi : 0x7fffffff;
        int mi = __reduce_min_sync(0xffffffffu, cand);
        if (lane == 0) s_key[par][warp] = make_key(wv, mi);

        __syncthreads();

        // Every thread redundantly reduces the 8 warp keys (broadcast LDS).
        const unsigned long long* k = s_key[par];
        unsigned long long m0 = umax64(k[0], k[1]);
        unsigned long long m1 = umax64(k[2], k[3]);
        unsigned long long m2 = umax64(k[4], k[5]);
        unsigned long long m3 = umax64(k[6], k[7]);
        keyreg = umax64(umax64(m0, m1), umax64(m2, m3));
    }
}

// ---------------------------------------------------------------------------
// Gather sampled points: out[0 .. B*M*3) = pts[b, d, idx[b,m]]
// ---------------------------------------------------------------------------
__global__ void gather_points_kernel(const float* __restrict__ pts,
                                     float* __restrict__ out)
{
    int g = blockIdx.x * blockDim.x + threadIdx.x;
    if (g >= NB * MS * 3) return;
    int d = g % 3;
    int m = (g / 3) % MS;
    int b = g / (3 * MS);
    int i = g_idx[b * MS + m];
    out[g] = pts[((size_t)b * 3 + d) * NP + i];
}

// ---------------------------------------------------------------------------
// Gather sampled features: out[B*M*3 + (b,m,c)] = feats[b, c, idx[b,m]]
// Coalesced float4 writes; reads are inherently scattered (random idx).
// ---------------------------------------------------------------------------
__global__ void gather_feats_kernel(const float* __restrict__ feats,
                                    float* __restrict__ out)
{
    const int C4 = NC / 4;                             // 64
    int g = blockIdx.x * blockDim.x + threadIdx.x;     // B*M*C4 total
    int c4 = g % C4;
    int m  = (g / C4) % MS;
    int b  = g / (C4 * MS);
    int i  = g_idx[b * MS + m];

    const float* f = feats + ((size_t)b * NC + (size_t)c4 * 4) * NP + i;
    float4 v;
    v.x = f[0];
    v.y = f[NP];
    v.z = f[2 * NP];
    v.w = f[3 * NP];
    reinterpret_cast<float4*>(out)[(NB * MS * 3) / 4 + g] = v;
}

// ---------------------------------------------------------------------------
extern "C" void kernel_launch(void* const* d_in, const int* in_sizes, int n_in,
                              void* d_out, int out_size)
{
    const float* pts   = (const float*)d_in[0];   // [B, 3, N]
    const float* feats = (const float*)d_in[1];   // [B, C, N]
    float* out = (float*)d_out;                   // [B*M*3] ++ [B*M*C]

    const size_t smem_bytes = (size_t)3 * NP * sizeof(float);   // 96 KB
    cudaFuncSetAttribute(fps_kernel,
                         cudaFuncAttributeMaxDynamicSharedMemorySize,
                         (int)smem_bytes);

    fps_kernel<<<NB, TPB, smem_bytes>>>(pts);

    gather_points_kernel<<<(NB * MS * 3 + 255) / 256, 256>>>(pts, out);

    const int feat_threads = NB * MS * (NC / 4);   // 2,097,152
    gather_feats_kernel<<<feat_threads / 256, 256>>>(feats, out);
}